// round 16
// baseline (speedup 1.0000x reference)
#include <cuda_runtime.h>
#include <math.h>
#include <stdint.h>

typedef unsigned long long u64;

// packed f32x2 helpers (sm_100+): two independent IEEE FMAs per instruction
__device__ __forceinline__ u64 pk2(float lo, float hi) {
    u64 r; asm("mov.b64 %0, {%1,%2};" : "=l"(r) : "f"(lo), "f"(hi)); return r;
}
__device__ __forceinline__ void fma2(u64& d, u64 a, u64 b) {
    asm("fma.rn.f32x2 %0, %1, %2, %0;" : "+l"(d) : "l"(a), "l"(b));
}
__device__ __forceinline__ float2 up2(u64 v) {
    float lo, hi; asm("mov.b64 {%0,%1}, %2;" : "=f"(lo), "=f"(hi) : "l"(v));
    return make_float2(lo, hi);
}
// cp.async 4B helper
__device__ __forceinline__ void cpa4(unsigned int dst, const float* src) {
    asm volatile("cp.async.ca.shared.global [%0], [%1], 4;" :: "r"(dst), "l"(src));
}
#define CP_COMMIT() asm volatile("cp.async.commit_group;" ::: "memory")
#define CP_WAIT0()  asm volatile("cp.async.wait_group 0;" ::: "memory")

// ---------------- scratch buffers (device globals; no allocation) ----------
__device__ float g_z1[32u*256u*64u*64u];
__device__ float g_A [32u*256u*32u*32u];
__device__ float g_B [32u*256u*32u*32u];
__device__ float g_C [32u*256u*32u*32u];
__device__ float g_loss;

__global__ void k_zero_loss() { g_loss = 0.0f; }

// ---------------- conv1: 3->256, k4 s2 p1, 128x128 -> 64x64, +bias ---------
__global__ __launch_bounds__(256) void k_conv1(const float* __restrict__ x,
                                               const float* __restrict__ w,
                                               const float* __restrict__ bias) {
    __shared__ __align__(16) float s_in[3][6][133];
    __shared__ __align__(16) float s_w[3][16][64];
    int t = threadIdx.x;
    int r0 = blockIdx.x * 2, oc0 = blockIdx.y * 64, b = blockIdx.z;

    for (int idx = t; idx < 3*6*130; idx += 256) {
        int ic = idx / 780, rem = idx % 780, rowi = rem / 130, coli = rem % 130;
        int ir = 2*r0 - 1 + rowi, icc = coli - 1;
        float v = 0.0f;
        if (ir >= 0 && ir < 128 && icc >= 0 && icc < 128)
            v = x[((b*3 + ic)*128 + ir)*128 + icc];
        s_in[ic][rowi][coli] = v;
    }
    for (int idx = t; idx < 3072; idx += 256) {
        int oc_l = idx / 48, rem = idx % 48;
        s_w[rem/16][rem%16][oc_l] = w[(oc0 + oc_l)*48 + rem];
    }
    __syncthreads();

    int ocg = t >> 5, pv = (t & 31) * 4;
    int row = pv >> 6, col = pv & 63;
    u64 acc2[4][4];
    #pragma unroll
    for (int i = 0; i < 4; i++)
        #pragma unroll
        for (int j = 0; j < 4; j++) acc2[i][j] = pk2(0.0f, 0.0f);

    #pragma unroll
    for (int ic = 0; ic < 3; ic++)
        #pragma unroll
        for (int ky = 0; ky < 4; ky++) {
            float iv10[10];
            #pragma unroll
            for (int m = 0; m < 10; m++)
                iv10[m] = s_in[ic][2*row + ky][2*col + m];
            u64 ivp[10];
            #pragma unroll
            for (int m = 0; m < 10; m++) ivp[m] = pk2(iv10[m], iv10[m]);
            #pragma unroll
            for (int kx = 0; kx < 4; kx++) {
                float4 w0 = *(const float4*)&s_w[ic][ky*4 + kx][ocg*8];
                float4 w1 = *(const float4*)&s_w[ic][ky*4 + kx][ocg*8 + 4];
                u64 wp[4] = {pk2(w0.x,w0.y), pk2(w0.z,w0.w), pk2(w1.x,w1.y), pk2(w1.z,w1.w)};
                #pragma unroll
                for (int i2 = 0; i2 < 4; i2++)
                    #pragma unroll
                    for (int j = 0; j < 4; j++) fma2(acc2[i2][j], wp[i2], ivp[2*j + kx]);
            }
        }

    int outr = r0 + row;
    #pragma unroll
    for (int i2 = 0; i2 < 4; i2++) {
        float2 q0 = up2(acc2[i2][0]), q1 = up2(acc2[i2][1]);
        float2 q2 = up2(acc2[i2][2]), q3 = up2(acc2[i2][3]);
        int ocA = oc0 + ocg*8 + 2*i2, ocB = ocA + 1;
        float bA = bias[ocA], bB = bias[ocB];
        float4 oA = make_float4(q0.x+bA, q1.x+bA, q2.x+bA, q3.x+bA);
        float4 oB = make_float4(q0.y+bB, q1.y+bB, q2.y+bB, q3.y+bB);
        *(float4*)&g_z1[((b*256 + ocA)*64 + outr)*64 + col] = oA;
        *(float4*)&g_z1[((b*256 + ocB)*64 + outr)*64 + col] = oB;
    }
}

// ------- conv2: 256->256, k4 s2 p1, 64x64 -> 32x32, +bias (pipelined) ------
__global__ __launch_bounds__(256, 2) void k_conv2(const float* __restrict__ w,
                                                  const float* __restrict__ bias,
                                                  float* __restrict__ out) {
    __shared__ __align__(16) float s_in[2][2][10][69];
    __shared__ __align__(16) float s_w[2][2][16][64];
    int t = threadIdx.x;
    int r0 = blockIdx.x * 4, oc0 = blockIdx.y * 64, b = blockIdx.z;
    int ocg = t >> 5, pv = (t & 31) * 4, row = pv >> 5, col = pv & 31;

    for (int idx = t; idx < 2*10*66; idx += 256) {
        int ic = idx / 660, rem = idx % 660, rowi = rem / 66, coli = rem % 66;
        int ir = 2*r0 - 1 + rowi, icc = coli - 1;
        float v = 0.0f;
        if (ir >= 0 && ir < 64 && icc >= 0 && icc < 64)
            v = g_z1[((b*256 + ic)*64 + ir)*64 + icc];
        s_in[0][ic][rowi][coli] = v;
    }
    for (int idx = t; idx < 2048; idx += 256) {
        int oc_l = idx >> 5, rem = idx & 31;
        s_w[0][rem >> 4][rem & 15][oc_l] = w[(oc0 + oc_l)*4096 + rem];
    }
    __syncthreads();

    u64 acc2[4][4];
    #pragma unroll
    for (int i = 0; i < 4; i++)
        #pragma unroll
        for (int j = 0; j < 4; j++) acc2[i][j] = pk2(0.0f, 0.0f);

    for (int ch = 0; ch < 128; ch++) {
        int cur = ch & 1;
        float rin[6], rw[8];
        if (ch < 127) {
            int ic0 = (ch + 1) * 2;
            #pragma unroll
            for (int s = 0; s < 6; s++) {
                int idx = t + s*256;
                float v = 0.0f;
                if (idx < 1320) {
                    int ic = idx / 660, rem = idx % 660, rowi = rem / 66, coli = rem % 66;
                    int ir = 2*r0 - 1 + rowi, icc = coli - 1;
                    if (ir >= 0 && ir < 64 && icc >= 0 && icc < 64)
                        v = g_z1[((b*256 + ic0 + ic)*64 + ir)*64 + icc];
                }
                rin[s] = v;
            }
            #pragma unroll
            for (int s = 0; s < 8; s++) {
                int idx = t + s*256;
                rw[s] = w[(oc0 + (idx >> 5))*4096 + ic0*16 + (idx & 31)];
            }
        }

        #pragma unroll
        for (int ic = 0; ic < 2; ic++)
            #pragma unroll
            for (int ky = 0; ky < 4; ky++) {
                float iv10[10];
                #pragma unroll
                for (int m = 0; m < 10; m++)
                    iv10[m] = s_in[cur][ic][2*row + ky][2*col + m];
                u64 ivp[10];
                #pragma unroll
                for (int m = 0; m < 10; m++) ivp[m] = pk2(iv10[m], iv10[m]);
                #pragma unroll
                for (int kx = 0; kx < 4; kx++) {
                    float4 w0 = *(const float4*)&s_w[cur][ic][ky*4 + kx][ocg*8];
                    float4 w1 = *(const float4*)&s_w[cur][ic][ky*4 + kx][ocg*8 + 4];
                    u64 wp[4] = {pk2(w0.x,w0.y), pk2(w0.z,w0.w), pk2(w1.x,w1.y), pk2(w1.z,w1.w)};
                    #pragma unroll
                    for (int i2 = 0; i2 < 4; i2++)
                        #pragma unroll
                        for (int j = 0; j < 4; j++) fma2(acc2[i2][j], wp[i2], ivp[2*j + kx]);
                }
            }

        if (ch < 127) {
            int nxt = cur ^ 1;
            #pragma unroll
            for (int s = 0; s < 6; s++) {
                int idx = t + s*256;
                if (idx < 1320) {
                    int ic = idx / 660, rem = idx % 660;
                    s_in[nxt][ic][rem / 66][rem % 66] = rin[s];
                }
            }
            #pragma unroll
            for (int s = 0; s < 8; s++) {
                int idx = t + s*256, rem = idx & 31;
                s_w[nxt][rem >> 4][rem & 15][idx >> 5] = rw[s];
            }
        }
        __syncthreads();
    }

    #pragma unroll
    for (int i2 = 0; i2 < 4; i2++) {
        float2 q0 = up2(acc2[i2][0]), q1 = up2(acc2[i2][1]);
        float2 q2 = up2(acc2[i2][2]), q3 = up2(acc2[i2][3]);
        int ocA = oc0 + ocg*8 + 2*i2, ocB = ocA + 1;
        float bA = bias[ocA], bB = bias[ocB];
        float4 oA = make_float4(q0.x+bA, q1.x+bA, q2.x+bA, q3.x+bA);
        float4 oB = make_float4(q0.y+bB, q1.y+bB, q2.y+bB, q3.y+bB);
        *(float4*)&out[((b*256 + ocA)*32 + r0 + row)*32 + col] = oA;
        *(float4*)&out[((b*256 + ocB)*32 + r0 + row)*32 + col] = oB;
    }
}

// ------- conv3x3: 256->256, relu-in, no bias, 32x32 (wide tile, chunk 4) ---
// thread = 1 row x 8 cols x 8 oc; ic-chunk 4 -> 64 iterations.
// inputs: reg-prefetch (relu applied at load); weights: cp.async into nxt buf.
__global__ __launch_bounds__(256, 2) void k_conv3(const float* __restrict__ in,
                                                  const float* __restrict__ w,
                                                  float* __restrict__ out) {
    __shared__ __align__(16) float s_in[2][4][10][35];
    __shared__ __align__(16) float s_w[2][4][9][64];
    int t = threadIdx.x;
    int r0 = blockIdx.x * 8, oc0 = blockIdx.y * 64, b = blockIdx.z;
    int ocg = t >> 5, lane = t & 31;
    int row = lane >> 2, col = (lane & 3) * 8;

    unsigned int sw_base = (unsigned int)__cvta_generic_to_shared(&s_w[0][0][0][0]);

    // stage ic 0..3 into buf0
    for (int idx = t; idx < 1360; idx += 256) {
        int ic = idx / 340, rem = idx % 340, rowi = rem / 34, coli = rem % 34;
        int ir = r0 - 1 + rowi, icc = coli - 1;
        float v = 0.0f;
        if (ir >= 0 && ir < 32 && icc >= 0 && icc < 32) {
            v = in[((b*256 + ic)*32 + ir)*32 + icc];
            v = v > 0.0f ? v : 0.0f;
        }
        s_in[0][ic][rowi][coli] = v;
    }
    for (int idx = t; idx < 2304; idx += 256) {
        int oc_l = idx / 36, rem = idx % 36;
        s_w[0][rem/9][rem%9][oc_l] = w[(oc0 + oc_l)*2304 + rem];
    }
    __syncthreads();

    u64 acc2[4][8];
    #pragma unroll
    for (int i = 0; i < 4; i++)
        #pragma unroll
        for (int j = 0; j < 8; j++) acc2[i][j] = pk2(0.0f, 0.0f);

    for (int ch = 0; ch < 64; ch++) {
        int cur = ch & 1;
        float rin[6];
        if (ch < 63) {
            int ic0 = (ch + 1) * 4;
            // weights: cp.async straight into nxt buffer (no transform needed)
            unsigned int wdst = sw_base + (unsigned int)(cur ^ 1) * (4*9*64*4);
            #pragma unroll
            for (int s = 0; s < 9; s++) {
                int idx = t + s*256;
                int oc_l = idx / 36, rem = idx % 36;
                cpa4(wdst + (unsigned int)(((rem/9)*9 + (rem%9))*64 + oc_l)*4,
                     &w[(oc0 + oc_l)*2304 + ic0*9 + rem]);
            }
            CP_COMMIT();
            // inputs: prefetch to regs with relu
            #pragma unroll
            for (int s = 0; s < 6; s++) {
                int idx = t + s*256;
                float v = 0.0f;
                if (idx < 1360) {
                    int ic = idx / 340, rem = idx % 340, rowi = rem / 34, coli = rem % 34;
                    int ir = r0 - 1 + rowi, icc = coli - 1;
                    if (ir >= 0 && ir < 32 && icc >= 0 && icc < 32) {
                        v = in[((b*256 + ic0 + ic)*32 + ir)*32 + icc];
                        v = v > 0.0f ? v : 0.0f;
                    }
                }
                rin[s] = v;
            }
        }

        #pragma unroll
        for (int ic = 0; ic < 4; ic++)
            #pragma unroll
            for (int ky = 0; ky < 3; ky++) {
                float iv[10];
                #pragma unroll
                for (int m = 0; m < 10; m++)
                    iv[m] = s_in[cur][ic][row + ky][col + m];
                u64 ivp[10];
                #pragma unroll
                for (int m = 0; m < 10; m++) ivp[m] = pk2(iv[m], iv[m]);
                #pragma unroll
                for (int kx = 0; kx < 3; kx++) {
                    float4 w0 = *(const float4*)&s_w[cur][ic][ky*3 + kx][ocg*8];
                    float4 w1 = *(const float4*)&s_w[cur][ic][ky*3 + kx][ocg*8 + 4];
                    u64 wp[4] = {pk2(w0.x,w0.y), pk2(w0.z,w0.w), pk2(w1.x,w1.y), pk2(w1.z,w1.w)};
                    #pragma unroll
                    for (int i2 = 0; i2 < 4; i2++)
                        #pragma unroll
                        for (int j = 0; j < 8; j++) fma2(acc2[i2][j], wp[i2], ivp[kx + j]);
                }
            }

        if (ch < 63) {
            int nxt = cur ^ 1;
            #pragma unroll
            for (int s = 0; s < 6; s++) {
                int idx = t + s*256;
                if (idx < 1360) {
                    int ic = idx / 340, rem = idx % 340;
                    s_in[nxt][ic][rem / 34][rem % 34] = rin[s];
                }
            }
            CP_WAIT0();
        }
        __syncthreads();
    }

    int orow = r0 + row;
    #pragma unroll
    for (int i2 = 0; i2 < 4; i2++) {
        float2 q[8];
        #pragma unroll
        for (int j = 0; j < 8; j++) q[j] = up2(acc2[i2][j]);
        int ocA = oc0 + ocg*8 + 2*i2, ocB = ocA + 1;
        float4 a0 = make_float4(q[0].x, q[1].x, q[2].x, q[3].x);
        float4 a1 = make_float4(q[4].x, q[5].x, q[6].x, q[7].x);
        float4 b0 = make_float4(q[0].y, q[1].y, q[2].y, q[3].y);
        float4 b1 = make_float4(q[4].y, q[5].y, q[6].y, q[7].y);
        *(float4*)&out[((b*256 + ocA)*32 + orow)*32 + col]     = a0;
        *(float4*)&out[((b*256 + ocA)*32 + orow)*32 + col + 4] = a1;
        *(float4*)&out[((b*256 + ocB)*32 + orow)*32 + col]     = b0;
        *(float4*)&out[((b*256 + ocB)*32 + orow)*32 + col + 4] = b1;
    }
}

// ------- conv1x1: 256->256, relu-in, + residual (pipelined, 2 CTAs/SM) -----
__global__ __launch_bounds__(256, 2) void k_c1x1(const float* __restrict__ in,
                                                 const float* __restrict__ w,
                                                 const float* __restrict__ resid,
                                                 float* __restrict__ out) {
    __shared__ __align__(16) float s_in[2][16][128];
    __shared__ __align__(16) float s_w[2][16][64];
    int t = threadIdx.x;
    int p0 = blockIdx.x * 128, oc0 = blockIdx.y * 64, b = blockIdx.z;
    int ocg = t >> 5, pp = (t & 31) * 4;

    for (int idx = t; idx < 2048; idx += 256) {
        int ic = idx >> 7, p = idx & 127;
        float v = in[(b*256 + ic)*1024 + p0 + p];
        s_in[0][ic][p] = v > 0.0f ? v : 0.0f;
    }
    for (int idx = t; idx < 1024; idx += 256) {
        int oc_l = idx >> 4, ic = idx & 15;
        s_w[0][ic][oc_l] = w[(oc0 + oc_l)*256 + ic];
    }
    __syncthreads();

    u64 acc2[4][4];
    #pragma unroll
    for (int i = 0; i < 4; i++)
        #pragma unroll
        for (int j = 0; j < 4; j++) acc2[i][j] = pk2(0.0f, 0.0f);

    for (int ch = 0; ch < 16; ch++) {
        int cur = ch & 1;
        float rin[8], rw[4];
        if (ch < 15) {
            int ic0 = (ch + 1) * 16;
            #pragma unroll
            for (int s = 0; s < 8; s++) {
                int idx = t + s*256;
                float v = in[(b*256 + ic0 + (idx >> 7))*1024 + p0 + (idx & 127)];
                rin[s] = v > 0.0f ? v : 0.0f;
            }
            #pragma unroll
            for (int s = 0; s < 4; s++) {
                int idx = t + s*256;
                rw[s] = w[(oc0 + (idx >> 4))*256 + ic0 + (idx & 15)];
            }
        }

        #pragma unroll
        for (int k = 0; k < 16; k++) {
            float4 ivv = *(const float4*)&s_in[cur][k][pp];
            u64 ivp[4] = {pk2(ivv.x,ivv.x), pk2(ivv.y,ivv.y), pk2(ivv.z,ivv.z), pk2(ivv.w,ivv.w)};
            float4 w0 = *(const float4*)&s_w[cur][k][ocg*8];
            float4 w1 = *(const float4*)&s_w[cur][k][ocg*8 + 4];
            u64 wp[4] = {pk2(w0.x,w0.y), pk2(w0.z,w0.w), pk2(w1.x,w1.y), pk2(w1.z,w1.w)};
            #pragma unroll
            for (int i2 = 0; i2 < 4; i2++)
                #pragma unroll
                for (int j = 0; j < 4; j++) fma2(acc2[i2][j], wp[i2], ivp[j]);
        }

        if (ch < 15) {
            int nxt = cur ^ 1;
            #pragma unroll
            for (int s = 0; s < 8; s++) {
                int idx = t + s*256;
                s_in[nxt][idx >> 7][idx & 127] = rin[s];
            }
            #pragma unroll
            for (int s = 0; s < 4; s++) {
                int idx = t + s*256;
                s_w[nxt][idx & 15][idx >> 4] = rw[s];
            }
        }
        __syncthreads();
    }

    #pragma unroll
    for (int i2 = 0; i2 < 4; i2++) {
        float2 q0 = up2(acc2[i2][0]), q1 = up2(acc2[i2][1]);
        float2 q2 = up2(acc2[i2][2]), q3 = up2(acc2[i2][3]);
        int ocA = oc0 + ocg*8 + 2*i2, ocB = ocA + 1;
        float4 rA = *(const float4*)&resid[(b*256 + ocA)*1024 + p0 + pp];
        float4 rB = *(const float4*)&resid[(b*256 + ocB)*1024 + p0 + pp];
        float4 oA = make_float4(q0.x+rA.x, q1.x+rA.y, q2.x+rA.z, q3.x+rA.w);
        float4 oB = make_float4(q0.y+rB.x, q1.y+rB.y, q2.y+rB.z, q3.y+rB.w);
        *(float4*)&out[(b*256 + ocA)*1024 + p0 + pp] = oA;
        *(float4*)&out[(b*256 + ocB)*1024 + p0 + pp] = oB;
    }
}

// ---------------- VQ: fp32 replica of reference distance (FROZEN) ----------
__global__ __launch_bounds__(256) void k_vq(const float* __restrict__ in,
                                            const float* __restrict__ cb,
                                            float* __restrict__ out) {
    __shared__ __align__(16) float s_v[64][65];
    __shared__ float s_vn[64];
    __shared__ float s_cn[64];
    __shared__ float s_dist[64];
    __shared__ int   s_fidx[64];
    __shared__ __align__(16) float s_cbuf[64*65];

    int t = threadIdx.x;
    int px0 = blockIdx.x * 64, cbk = blockIdx.y, b = blockIdx.z;
    const float* base = in + (b*256 + cbk*64)*1024 + px0;

    for (int idx = t; idx < 4096; idx += 256) {
        int j = idx >> 6, i = idx & 63;
        s_v[i][j] = base[j*1024 + i];
    }
    __syncthreads();
    if (t < 64) {
        float s = 0.0f;
        for (int j = 0; j < 64; j++) { float v = s_v[t][j]; s = __fmaf_rn(v, v, s); }
        s_vn[t] = s;
    }
    __syncthreads();

    int i0 = (t & 7) * 8;
    int g  = t >> 3;
    float vn[8];
    #pragma unroll
    for (int ii = 0; ii < 8; ii++) vn[ii] = s_vn[i0 + ii];

    float best[8]; int bidx[8];
    #pragma unroll
    for (int ii = 0; ii < 8; ii++) { best[ii] = 3.4e38f; bidx[ii] = 0x7fffffff; }

    for (int chunk = 0; chunk < 4; chunk++) {
        __syncthreads();
        for (int idx = t; idx < 4096; idx += 256) {
            int cc = idx >> 6, j = idx & 63;
            s_cbuf[cc*65 + j] = cb[(chunk*64 + cc)*64 + j];
        }
        __syncthreads();
        if (t < 64) {
            float s = 0.0f;
            for (int j = 0; j < 64; j++) { float e = s_cbuf[t*65 + j]; s = __fmaf_rn(e, e, s); }
            s_cn[t] = s;
        }
        __syncthreads();

        int cc0 = g * 2;
        float d0[8], d1[8];
        #pragma unroll
        for (int ii = 0; ii < 8; ii++) { d0[ii] = 0.0f; d1[ii] = 0.0f; }
        for (int k = 0; k < 64; k++) {
            float c0 = s_cbuf[cc0*65 + k];
            float c1 = s_cbuf[(cc0+1)*65 + k];
            #pragma unroll
            for (int ii = 0; ii < 8; ii++) {
                float vv = s_v[i0 + ii][k];
                d0[ii] = __fmaf_rn(vv, c0, d0[ii]);
                d1[ii] = __fmaf_rn(vv, c1, d1[ii]);
            }
        }
        float n0 = s_cn[cc0], n1 = s_cn[cc0+1];
        #pragma unroll
        for (int ii = 0; ii < 8; ii++) {
            float sc0 = __fsub_rn(__fadd_rn(vn[ii], n0), __fmul_rn(2.0f, d0[ii]));
            if (sc0 < best[ii]) { best[ii] = sc0; bidx[ii] = chunk*64 + cc0; }
            float sc1 = __fsub_rn(__fadd_rn(vn[ii], n1), __fmul_rn(2.0f, d1[ii]));
            if (sc1 < best[ii]) { best[ii] = sc1; bidx[ii] = chunk*64 + cc0 + 1; }
        }
    }
    __syncthreads();

    float* rv = s_cbuf;
    int*   ri = (int*)(s_cbuf + 2048);
    #pragma unroll
    for (int ii = 0; ii < 8; ii++) {
        rv[g*64 + i0 + ii] = best[ii];
        ri[g*64 + i0 + ii] = bidx[ii];
    }
    __syncthreads();

    if (t < 64) {
        float bb = 3.4e38f; int bi = 0x7fffffff;
        for (int gg = 0; gg < 32; gg++) {
            float v = rv[gg*64 + t];
            int  id = ri[gg*64 + t];
            if (v < bb || (v == bb && id < bi)) { bb = v; bi = id; }
        }
        s_fidx[t] = bi;
        s_dist[t] = bb;
    }
    __syncthreads();
    if (t == 0) {
        float s = 0.0f;
        for (int v = 0; v < 64; v++) s += s_dist[v];
        atomicAdd(&g_loss, s);
    }

    for (int idx = t; idx < 4096; idx += 256) {
        int j = idx >> 6, i = idx & 63;
        out[(b*256 + cbk*64 + j)*1024 + px0 + i] = cb[s_fidx[i]*64 + j];
    }
}

// ------- deconv1: 256->256, transposed (wide tile, 2 CTAs/SM) --------------
__global__ __launch_bounds__(256, 2) void k_deconv1(const float* __restrict__ in,
                                                    const float* __restrict__ w,
                                                    const float* __restrict__ bias) {
    __shared__ __align__(16) float s_in[2][4][9][33];
    __shared__ __align__(16) float s_w[2][4][4][64];
    int t = threadIdx.x;
    int r0 = blockIdx.x * 8, oc0 = blockIdx.y * 64;
    int bz = blockIdx.z, b = bz >> 2, cls = bz & 3, py = cls >> 1, qx = cls & 1;
    int ocg = t >> 5, lane = t & 31;
    int row = lane >> 2, col = (lane & 3) * 8;

    for (int idx = t; idx < 1188; idx += 256) {
        int ic = idx / 297, rem = idx % 297, rowi = rem / 33, coli = rem % 33;
        int ir = r0 + py - 1 + rowi, icc = qx - 1 + coli;
        float v = 0.0f;
        if (ir >= 0 && ir < 32 && icc >= 0 && icc < 32)
            v = in[((b*256 + ic)*32 + ir)*32 + icc];
        s_in[0][ic][rowi][coli] = v;
    }
    for (int idx = t; idx < 1024; idx += 256) {
        int ic = idx >> 8, rem = idx & 255, oc_l = rem >> 2, tp = rem & 3;
        int dy = tp >> 1, dx = tp & 1;
        s_w[0][ic][tp][oc_l] =
            w[(ic*256 + oc0 + oc_l)*16 + (3 - py - 2*dy)*4 + (3 - qx - 2*dx)];
    }
    __syncthreads();

    u64 acc2[4][8];
    #pragma unroll
    for (int i = 0; i < 4; i++)
        #pragma unroll
        for (int j = 0; j < 8; j++) acc2[i][j] = pk2(0.0f, 0.0f);

    for (int ch = 0; ch < 64; ch++) {
        int cur = ch & 1;
        float rin[5], rw[4];
        if (ch < 63) {
            int ic0 = (ch + 1) * 4;
            #pragma unroll
            for (int s = 0; s < 5; s++) {
                int idx = t + s*256;
                float v = 0.0f;
                if (idx < 1188) {
                    int ic = idx / 297, rem = idx % 297, rowi = rem / 33, coli = rem % 33;
                    int ir = r0 + py - 1 + rowi, icc = qx - 1 + coli;
                    if (ir >= 0 && ir < 32 && icc >= 0 && icc < 32)
                        v = in[((b*256 + ic0 + ic)*32 + ir)*32 + icc];
                }
                rin[s] = v;
            }
            #pragma unroll
            for (int s = 0; s < 4; s++) {
                int idx = t + s*256;
                int ic = idx >> 8, rem = idx & 255, oc_l = rem >> 2, tp = rem & 3;
                int dy = tp >> 1, dx = tp & 1;
                rw[s] = w[((ic0 + ic)*256 + oc0 + oc_l)*16 + (3 - py - 2*dy)*4 + (3 - qx - 2*dx)];
            }
        }

        #pragma unroll
        for (int ic = 0; ic < 4; ic++)
            #pragma unroll
            for (int dy = 0; dy < 2; dy++) {
                float iv[9];
                #pragma unroll
                for (int m = 0; m < 9; m++)
                    iv[m] = s_in[cur][ic][row + dy][col + m];
                u64 ivp[9];
                #pragma unroll
                for (int m = 0; m < 9; m++) ivp[m] = pk2(iv[m], iv[m]);
                #pragma unroll
                for (int dx = 0; dx < 2; dx++) {
                    float4 w0 = *(const float4*)&s_w[cur][ic][dy*2 + dx][ocg*8];
                    float4 w1 = *(const float4*)&s_w[cur][ic][dy*2 + dx][ocg*8 + 4];
                    u64 wp[4] = {pk2(w0.x,w0.y), pk2(w0.z,w0.w), pk2(w1.x,w1.y), pk2(w1.z,w1.w)};
                    #pragma unroll
                    for (int i2 = 0; i2 < 4; i2++)
                        #pragma unroll
                        for (int j = 0; j < 8; j++) fma2(acc2[i2][j], wp[i2], ivp[j + dx]);
                }
            }

        if (ch < 63) {
            int nxt = cur ^ 1;
            #pragma unroll
            for (int s = 0; s < 5; s++) {
                int idx = t + s*256;
                if (idx < 1188) {
                    int ic = idx / 297, rem = idx % 297;
                    s_in[nxt][ic][rem / 33][rem % 33] = rin[s];
                }
            }
            #pragma unroll
            for (int s = 0; s < 4; s++) {
                int idx = t + s*256;
                int ic = idx >> 8, rem = idx & 255;
                s_w[nxt][ic][rem & 3][rem >> 2] = rw[s];
            }
        }
        __syncthreads();
    }

    int oy = 2*(r0 + row) + py;
    #pragma unroll
    for (int i2 = 0; i2 < 4; i2++) {
        float2 q[8];
        #pragma unroll
        for (int j = 0; j < 8; j++) q[j] = up2(acc2[i2][j]);
        int ocA = oc0 + ocg*8 + 2*i2, ocB = ocA + 1;
        float bA = bias[ocA], bB = bias[ocB];
        #pragma unroll
        for (int j = 0; j < 8; j++) {
            int ox = 2*(col + j) + qx;
            g_z1[((b*256 + ocA)*64 + oy)*64 + ox] = q[j].x + bA;
            g_z1[((b*256 + ocB)*64 + oy)*64 + ox] = q[j].y + bB;
        }
    }
}

// ------- deconv2: 256->3, transposed, 64->128, +bias, tanh (pipelined) -----
__global__ __launch_bounds__(256, 2) void k_deconv2(const float* __restrict__ w,
                                                    const float* __restrict__ bias,
                                                    float* __restrict__ out) {
    __shared__ float s_in[2][4][17][69];
    __shared__ float s_w[2][4][4][3];
    int t = threadIdx.x;
    int r0 = blockIdx.x * 16;
    int bz = blockIdx.z, b = bz >> 2, cls = bz & 3, py = cls >> 1, qx = cls & 1;
    int pv = t * 4, row = pv >> 6, col = pv & 63;

    for (int idx = t; idx < 4420; idx += 256) {
        int ic = idx / 1105, rem = idx % 1105, rowi = rem / 65, coli = rem % 65;
        int ir = r0 + py - 1 + rowi, icc = qx - 1 + coli;
        float v = 0.0f;
        if (ir >= 0 && ir < 64 && icc >= 0 && icc < 64)
            v = g_z1[((b*256 + ic)*64 + ir)*64 + icc];
        s_in[0][ic][rowi][coli] = v;
    }
    if (t < 48) {
        int ic = t / 12, rem = t % 12, oc = rem / 4, tp = rem & 3;
        int dy = tp >> 1, dx = tp & 1;
        s_w[0][ic][tp][oc] =
            w[(ic*3 + oc)*16 + (3 - py - 2*dy)*4 + (3 - qx - 2*dx)];
    }
    __syncthreads();

    float acc[3][4];
    #pragma unroll
    for (int i = 0; i < 3; i++)
        #pragma unroll
        for (int j = 0; j < 4; j++) acc[i][j] = 0.0f;

    for (int ch = 0; ch < 64; ch++) {
        int cur = ch & 1;
        float rin[18], rwv = 0.0f;
        if (ch < 63) {
            int ic0n = (ch + 1) * 4;
            #pragma unroll
            for (int s = 0; s < 18; s++) {
                int idx = t + s*256;
                float v = 0.0f;
                if (idx < 4420) {
                    int ic = idx / 1105, rem = idx % 1105, rowi = rem / 65, coli = rem % 65;
                    int ir = r0 + py - 1 + rowi, icc = qx - 1 + coli;
                    if (ir >= 0 && ir < 64 && icc >= 0 && icc < 64)
                        v = g_z1[((b*256 + ic0n + ic)*64 + ir)*64 + icc];
                }
                rin[s] = v;
            }
            if (t < 48) {
                int ic = t / 12, rem = t % 12, oc = rem / 4, tp = rem & 3;
                int dy = tp >> 1, dx = tp & 1;
                rwv = w[((ic0n + ic)*3 + oc)*16 + (3 - py - 2*dy)*4 + (3 - qx - 2*dx)];
            }
        }

        #pragma unroll
        for (int ic = 0; ic < 4; ic++)
            #pragma unroll
            for (int dy = 0; dy < 2; dy++) {
                float iv5[5];
                #pragma unroll
                for (int m = 0; m < 5; m++)
                    iv5[m] = s_in[cur][ic][row + dy][col + m];
                #pragma unroll
                for (int dx = 0; dx < 2; dx++) {
                    #pragma unroll
                    for (int oc = 0; oc < 3; oc++) {
                        float wv = s_w[cur][ic][dy*2 + dx][oc];
                        #pragma unroll
                        for (int j = 0; j < 4; j++) acc[oc][j] += wv * iv5[j + dx];
                    }
                }
            }

        if (ch < 63) {
            int nxt = cur ^ 1;
            #pragma unroll
            for (int s = 0; s < 18; s++) {
                int idx = t + s*256;
                if (idx < 4420) {
                    int ic = idx / 1105, rem = idx % 1105;
                    s_in[nxt][ic][rem / 65][rem % 65] = rin[s];
                }
            }
            if (t < 48) {
                int ic = t / 12, rem = t % 12, oc = rem / 4, tp = rem & 3;
                s_w[nxt][ic][tp][oc] = rwv;
            }
        }
        __syncthreads();
    }

    int oy = 2*(r0 + row) + py;
    #pragma unroll
    for (int oc = 0; oc < 3; oc++) {
        float bv = bias[oc];
        #pragma unroll
        for (int j = 0; j < 4; j++) {
            int ox = 2*(col + j) + qx;
            out[((b*3 + oc)*128 + oy)*128 + ox] = tanhf(acc[oc][j] + bv);
        }
    }
}

__global__ void k_finalize(float* out, int n) {
    out[n - 1] = 1.25f * g_loss / 8388608.0f;
}

// ---------------------------------------------------------------------------
extern "C" void kernel_launch(void* const* d_in, const int* in_sizes, int n_in,
                              void* d_out, int out_size) {
    const float* x       = (const float*)d_in[0];
    const float* enc_w1  = (const float*)d_in[1];
    const float* enc_b1  = (const float*)d_in[2];
    const float* enc_w2  = (const float*)d_in[3];
    const float* enc_b2  = (const float*)d_in[4];
    const float* er1_w3  = (const float*)d_in[5];
    const float* er1_w1  = (const float*)d_in[6];
    const float* er2_w3  = (const float*)d_in[7];
    const float* er2_w1  = (const float*)d_in[8];
    const float* codebook= (const float*)d_in[9];
    const float* dr1_w3  = (const float*)d_in[10];
    const float* dr1_w1  = (const float*)d_in[11];
    const float* dr2_w3  = (const float*)d_in[12];
    const float* dr2_w1  = (const float*)d_in[13];
    const float* dt1_w   = (const float*)d_in[14];
    const float* dt1_b   = (const float*)d_in[15];
    const float* dt2_w   = (const float*)d_in[16];
    const float* dt2_b   = (const float*)d_in[17];
    float* out = (float*)d_out;

    float *pA, *pB, *pC;
    cudaGetSymbolAddress((void**)&pA, g_A);
    cudaGetSymbolAddress((void**)&pB, g_B);
    cudaGetSymbolAddress((void**)&pC, g_C);

    k_zero_loss<<<1, 1>>>();

    // encoder
    k_conv1<<<dim3(32, 4, 32), 256>>>(x, enc_w1, enc_b1);
    k_conv2<<<dim3(8, 4, 32), 256>>>(enc_w2, enc_b2, pA);
    k_conv3<<<dim3(4, 4, 32), 256>>>(pA, er1_w3, pB);
    k_c1x1 <<<dim3(8, 4, 32), 256>>>(pB, er1_w1, pA, pC);
    k_conv3<<<dim3(4, 4, 32), 256>>>(pC, er2_w3, pB);
    k_c1x1 <<<dim3(8, 4, 32), 256>>>(pB, er2_w1, pC, pA);

    // VQ
    k_vq<<<dim3(16, 4, 32), 256>>>(pA, codebook, pC);

    // decoder
    k_conv3<<<dim3(4, 4, 32), 256>>>(pC, dr1_w3, pB);
    k_c1x1 <<<dim3(8, 4, 32), 256>>>(pB, dr1_w1, pC, pA);
    k_conv3<<<dim3(4, 4, 32), 256>>>(pA, dr2_w3, pB);
    k_c1x1 <<<dim3(8, 4, 32), 256>>>(pB, dr2_w1, pA, pC);
    k_deconv1<<<dim3(4, 4, 128), 256>>>(pC, dt1_w, dt1_b);
    k_deconv2<<<dim3(4, 1, 128), 256>>>(dt2_w, dt2_b, out);

    k_finalize<<<1, 1>>>(out, out_size);
}

// round 17
// speedup vs baseline: 1.0501x; 1.0501x over previous
#include <cuda_runtime.h>
#include <math.h>
#include <stdint.h>

typedef unsigned long long u64;

// packed f32x2 helpers (sm_100+): two independent IEEE FMAs per instruction
__device__ __forceinline__ u64 pk2(float lo, float hi) {
    u64 r; asm("mov.b64 %0, {%1,%2};" : "=l"(r) : "f"(lo), "f"(hi)); return r;
}
__device__ __forceinline__ void fma2(u64& d, u64 a, u64 b) {
    asm("fma.rn.f32x2 %0, %1, %2, %0;" : "+l"(d) : "l"(a), "l"(b));
}
__device__ __forceinline__ float2 up2(u64 v) {
    float lo, hi; asm("mov.b64 {%0,%1}, %2;" : "=f"(lo), "=f"(hi) : "l"(v));
    return make_float2(lo, hi);
}

// ---------------- scratch buffers (device globals; no allocation) ----------
__device__ float g_z1[32u*256u*64u*64u];
__device__ float g_A [32u*256u*32u*32u];
__device__ float g_B [32u*256u*32u*32u];
__device__ float g_C [32u*256u*32u*32u];
__device__ float g_loss;

__global__ void k_zero_loss() { g_loss = 0.0f; }

// ---------------- conv1: 3->256, k4 s2 p1, 128x128 -> 64x64, +bias ---------
__global__ __launch_bounds__(256) void k_conv1(const float* __restrict__ x,
                                               const float* __restrict__ w,
                                               const float* __restrict__ bias) {
    __shared__ __align__(16) float s_in[3][6][133];
    __shared__ __align__(16) float s_w[3][16][64];
    int t = threadIdx.x;
    int r0 = blockIdx.x * 2, oc0 = blockIdx.y * 64, b = blockIdx.z;

    for (int idx = t; idx < 3*6*130; idx += 256) {
        int ic = idx / 780, rem = idx % 780, rowi = rem / 130, coli = rem % 130;
        int ir = 2*r0 - 1 + rowi, icc = coli - 1;
        float v = 0.0f;
        if (ir >= 0 && ir < 128 && icc >= 0 && icc < 128)
            v = x[((b*3 + ic)*128 + ir)*128 + icc];
        s_in[ic][rowi][coli] = v;
    }
    for (int idx = t; idx < 3072; idx += 256) {
        int oc_l = idx / 48, rem = idx % 48;
        s_w[rem/16][rem%16][oc_l] = w[(oc0 + oc_l)*48 + rem];
    }
    __syncthreads();

    int ocg = t >> 5, pv = (t & 31) * 4;
    int row = pv >> 6, col = pv & 63;
    u64 acc2[4][4];
    #pragma unroll
    for (int i = 0; i < 4; i++)
        #pragma unroll
        for (int j = 0; j < 4; j++) acc2[i][j] = pk2(0.0f, 0.0f);

    #pragma unroll
    for (int ic = 0; ic < 3; ic++)
        #pragma unroll
        for (int ky = 0; ky < 4; ky++) {
            float iv10[10];
            #pragma unroll
            for (int m = 0; m < 10; m++)
                iv10[m] = s_in[ic][2*row + ky][2*col + m];
            u64 ivp[10];
            #pragma unroll
            for (int m = 0; m < 10; m++) ivp[m] = pk2(iv10[m], iv10[m]);
            #pragma unroll
            for (int kx = 0; kx < 4; kx++) {
                float4 w0 = *(const float4*)&s_w[ic][ky*4 + kx][ocg*8];
                float4 w1 = *(const float4*)&s_w[ic][ky*4 + kx][ocg*8 + 4];
                u64 wp[4] = {pk2(w0.x,w0.y), pk2(w0.z,w0.w), pk2(w1.x,w1.y), pk2(w1.z,w1.w)};
                #pragma unroll
                for (int i2 = 0; i2 < 4; i2++)
                    #pragma unroll
                    for (int j = 0; j < 4; j++) fma2(acc2[i2][j], wp[i2], ivp[2*j + kx]);
            }
        }

    int outr = r0 + row;
    #pragma unroll
    for (int i2 = 0; i2 < 4; i2++) {
        float2 q0 = up2(acc2[i2][0]), q1 = up2(acc2[i2][1]);
        float2 q2 = up2(acc2[i2][2]), q3 = up2(acc2[i2][3]);
        int ocA = oc0 + ocg*8 + 2*i2, ocB = ocA + 1;
        float bA = bias[ocA], bB = bias[ocB];
        float4 oA = make_float4(q0.x+bA, q1.x+bA, q2.x+bA, q3.x+bA);
        float4 oB = make_float4(q0.y+bB, q1.y+bB, q2.y+bB, q3.y+bB);
        *(float4*)&g_z1[((b*256 + ocA)*64 + outr)*64 + col] = oA;
        *(float4*)&g_z1[((b*256 + ocB)*64 + outr)*64 + col] = oB;
    }
}

// ------- conv2: 256->256, k4 s2 p1, 64x64 -> 32x32 (WIDE 8-col tile) -------
// thread = 1 row x 8 cols x 8 oc; block = 8 rows x 32 cols x 64 oc.
// ic-chunk 2, 128 iterations, double-buffered, reg-prefetch. 2 CTAs/SM.
__global__ __launch_bounds__(256, 2) void k_conv2(const float* __restrict__ w,
                                                  const float* __restrict__ bias,
                                                  float* __restrict__ out) {
    __shared__ __align__(16) float s_in[2][2][18][67];
    __shared__ __align__(16) float s_w[2][2][16][64];
    int t = threadIdx.x;
    int r0 = blockIdx.x * 8, oc0 = blockIdx.y * 64, b = blockIdx.z;
    int ocg = t >> 5, lane = t & 31;
    int row = lane >> 2, col = (lane & 3) * 8;

    // stage ic 0..1 into buf0 (input rows 2*r0-1 .. 2*r0+16, cols -1..64)
    for (int idx = t; idx < 2376; idx += 256) {
        int ic = idx / 1188, rem = idx % 1188, rowi = rem / 66, coli = rem % 66;
        int ir = 2*r0 - 1 + rowi, icc = coli - 1;
        float v = 0.0f;
        if (ir >= 0 && ir < 64 && icc >= 0 && icc < 64)
            v = g_z1[((b*256 + ic)*64 + ir)*64 + icc];
        s_in[0][ic][rowi][coli] = v;
    }
    for (int idx = t; idx < 2048; idx += 256) {
        int oc_l = idx >> 5, rem = idx & 31;
        s_w[0][rem >> 4][rem & 15][oc_l] = w[(oc0 + oc_l)*4096 + rem];
    }
    __syncthreads();

    u64 acc2[4][8];
    #pragma unroll
    for (int i = 0; i < 4; i++)
        #pragma unroll
        for (int j = 0; j < 8; j++) acc2[i][j] = pk2(0.0f, 0.0f);

    for (int ch = 0; ch < 128; ch++) {
        int cur = ch & 1;
        float rin[10], rw[8];
        if (ch < 127) {
            int ic0 = (ch + 1) * 2;
            #pragma unroll
            for (int s = 0; s < 10; s++) {
                int idx = t + s*256;
                float v = 0.0f;
                if (idx < 2376) {
                    int ic = idx / 1188, rem = idx % 1188, rowi = rem / 66, coli = rem % 66;
                    int ir = 2*r0 - 1 + rowi, icc = coli - 1;
                    if (ir >= 0 && ir < 64 && icc >= 0 && icc < 64)
                        v = g_z1[((b*256 + ic0 + ic)*64 + ir)*64 + icc];
                }
                rin[s] = v;
            }
            #pragma unroll
            for (int s = 0; s < 8; s++) {
                int idx = t + s*256;
                rw[s] = w[(oc0 + (idx >> 5))*4096 + ic0*16 + (idx & 31)];
            }
        }

        #pragma unroll
        for (int ic = 0; ic < 2; ic++)
            #pragma unroll
            for (int ky = 0; ky < 4; ky++) {
                float iv[18];
                #pragma unroll
                for (int m = 0; m < 18; m++)
                    iv[m] = s_in[cur][ic][2*row + ky][2*col + m];
                #pragma unroll
                for (int kx = 0; kx < 4; kx++) {
                    float4 w0 = *(const float4*)&s_w[cur][ic][ky*4 + kx][ocg*8];
                    float4 w1 = *(const float4*)&s_w[cur][ic][ky*4 + kx][ocg*8 + 4];
                    u64 wp[4] = {pk2(w0.x,w0.y), pk2(w0.z,w0.w), pk2(w1.x,w1.y), pk2(w1.z,w1.w)};
                    u64 ivp8[8];
                    #pragma unroll
                    for (int j = 0; j < 8; j++) ivp8[j] = pk2(iv[2*j + kx], iv[2*j + kx]);
                    #pragma unroll
                    for (int i2 = 0; i2 < 4; i2++)
                        #pragma unroll
                        for (int j = 0; j < 8; j++) fma2(acc2[i2][j], wp[i2], ivp8[j]);
                }
            }

        if (ch < 127) {
            int nxt = cur ^ 1;
            #pragma unroll
            for (int s = 0; s < 10; s++) {
                int idx = t + s*256;
                if (idx < 2376) {
                    int ic = idx / 1188, rem = idx % 1188;
                    s_in[nxt][ic][rem / 66][rem % 66] = rin[s];
                }
            }
            #pragma unroll
            for (int s = 0; s < 8; s++) {
                int idx = t + s*256, rem = idx & 31;
                s_w[nxt][rem >> 4][rem & 15][idx >> 5] = rw[s];
            }
        }
        __syncthreads();
    }

    int orow = r0 + row;
    #pragma unroll
    for (int i2 = 0; i2 < 4; i2++) {
        float2 q[8];
        #pragma unroll
        for (int j = 0; j < 8; j++) q[j] = up2(acc2[i2][j]);
        int ocA = oc0 + ocg*8 + 2*i2, ocB = ocA + 1;
        float bA = bias[ocA], bB = bias[ocB];
        float4 a0 = make_float4(q[0].x+bA, q[1].x+bA, q[2].x+bA, q[3].x+bA);
        float4 a1 = make_float4(q[4].x+bA, q[5].x+bA, q[6].x+bA, q[7].x+bA);
        float4 b0 = make_float4(q[0].y+bB, q[1].y+bB, q[2].y+bB, q[3].y+bB);
        float4 b1 = make_float4(q[4].y+bB, q[5].y+bB, q[6].y+bB, q[7].y+bB);
        *(float4*)&out[((b*256 + ocA)*32 + orow)*32 + col]     = a0;
        *(float4*)&out[((b*256 + ocA)*32 + orow)*32 + col + 4] = a1;
        *(float4*)&out[((b*256 + ocB)*32 + orow)*32 + col]     = b0;
        *(float4*)&out[((b*256 + ocB)*32 + orow)*32 + col + 4] = b1;
    }
}

// ------- conv3x3: 256->256, relu-in, no bias, 32x32 (wide 8-col tile) ------
// REVERTED to Round-14 proven version (chunk 2, reg-prefetch, 2 CTAs/SM).
__global__ __launch_bounds__(256, 2) void k_conv3(const float* __restrict__ in,
                                                  const float* __restrict__ w,
                                                  float* __restrict__ out) {
    __shared__ __align__(16) float s_in[2][2][10][35];
    __shared__ __align__(16) float s_w[2][2][9][64];
    int t = threadIdx.x;
    int r0 = blockIdx.x * 8, oc0 = blockIdx.y * 64, b = blockIdx.z;
    int ocg = t >> 5, lane = t & 31;
    int row = lane >> 2, col = (lane & 3) * 8;

    for (int idx = t; idx < 680; idx += 256) {
        int ic = idx / 340, rem = idx % 340, rowi = rem / 34, coli = rem % 34;
        int ir = r0 - 1 + rowi, icc = coli - 1;
        float v = 0.0f;
        if (ir >= 0 && ir < 32 && icc >= 0 && icc < 32) {
            v = in[((b*256 + ic)*32 + ir)*32 + icc];
            v = v > 0.0f ? v : 0.0f;
        }
        s_in[0][ic][rowi][coli] = v;
    }
    for (int idx = t; idx < 1152; idx += 256) {
        int oc_l = idx / 18, rem = idx % 18;
        s_w[0][rem/9][rem%9][oc_l] = w[(oc0 + oc_l)*2304 + rem];
    }
    __syncthreads();

    u64 acc2[4][8];
    #pragma unroll
    for (int i = 0; i < 4; i++)
        #pragma unroll
        for (int j = 0; j < 8; j++) acc2[i][j] = pk2(0.0f, 0.0f);

    for (int ch = 0; ch < 128; ch++) {
        int cur = ch & 1;
        float rin[3], rw[5];
        if (ch < 127) {
            int ic0 = (ch + 1) * 2;
            #pragma unroll
            for (int s = 0; s < 3; s++) {
                int idx = t + s*256;
                float v = 0.0f;
                if (idx < 680) {
                    int ic = idx / 340, rem = idx % 340, rowi = rem / 34, coli = rem % 34;
                    int ir = r0 - 1 + rowi, icc = coli - 1;
                    if (ir >= 0 && ir < 32 && icc >= 0 && icc < 32) {
                        v = in[((b*256 + ic0 + ic)*32 + ir)*32 + icc];
                        v = v > 0.0f ? v : 0.0f;
                    }
                }
                rin[s] = v;
            }
            #pragma unroll
            for (int s = 0; s < 5; s++) {
                int idx = t + s*256;
                rw[s] = (idx < 1152) ? w[(oc0 + idx/18)*2304 + ic0*9 + (idx%18)] : 0.0f;
            }
        }

        #pragma unroll
        for (int ic = 0; ic < 2; ic++)
            #pragma unroll
            for (int ky = 0; ky < 3; ky++) {
                float iv[10];
                #pragma unroll
                for (int m = 0; m < 10; m++)
                    iv[m] = s_in[cur][ic][row + ky][col + m];
                u64 ivp[10];
                #pragma unroll
                for (int m = 0; m < 10; m++) ivp[m] = pk2(iv[m], iv[m]);
                #pragma unroll
                for (int kx = 0; kx < 3; kx++) {
                    float4 w0 = *(const float4*)&s_w[cur][ic][ky*3 + kx][ocg*8];
                    float4 w1 = *(const float4*)&s_w[cur][ic][ky*3 + kx][ocg*8 + 4];
                    u64 wp[4] = {pk2(w0.x,w0.y), pk2(w0.z,w0.w), pk2(w1.x,w1.y), pk2(w1.z,w1.w)};
                    #pragma unroll
                    for (int i2 = 0; i2 < 4; i2++)
                        #pragma unroll
                        for (int j = 0; j < 8; j++) fma2(acc2[i2][j], wp[i2], ivp[kx + j]);
                }
            }

        if (ch < 127) {
            int nxt = cur ^ 1;
            #pragma unroll
            for (int s = 0; s < 3; s++) {
                int idx = t + s*256;
                if (idx < 680) {
                    int ic = idx / 340, rem = idx % 340;
                    s_in[nxt][ic][rem / 34][rem % 34] = rin[s];
                }
            }
            #pragma unroll
            for (int s = 0; s < 5; s++) {
                int idx = t + s*256;
                if (idx < 1152) {
                    int rem = idx % 18;
                    s_w[nxt][rem/9][rem%9][idx/18] = rw[s];
                }
            }
        }
        __syncthreads();
    }

    int orow = r0 + row;
    #pragma unroll
    for (int i2 = 0; i2 < 4; i2++) {
        float2 q[8];
        #pragma unroll
        for (int j = 0; j < 8; j++) q[j] = up2(acc2[i2][j]);
        int ocA = oc0 + ocg*8 + 2*i2, ocB = ocA + 1;
        float4 a0 = make_float4(q[0].x, q[1].x, q[2].x, q[3].x);
        float4 a1 = make_float4(q[4].x, q[5].x, q[6].x, q[7].x);
        float4 b0 = make_float4(q[0].y, q[1].y, q[2].y, q[3].y);
        float4 b1 = make_float4(q[4].y, q[5].y, q[6].y, q[7].y);
        *(float4*)&out[((b*256 + ocA)*32 + orow)*32 + col]     = a0;
        *(float4*)&out[((b*256 + ocA)*32 + orow)*32 + col + 4] = a1;
        *(float4*)&out[((b*256 + ocB)*32 + orow)*32 + col]     = b0;
        *(float4*)&out[((b*256 + ocB)*32 + orow)*32 + col + 4] = b1;
    }
}

// ------- conv1x1: 256->256, relu-in, + residual (pipelined, 2 CTAs/SM) -----
__global__ __launch_bounds__(256, 2) void k_c1x1(const float* __restrict__ in,
                                                 const float* __restrict__ w,
                                                 const float* __restrict__ resid,
                                                 float* __restrict__ out) {
    __shared__ __align__(16) float s_in[2][16][128];
    __shared__ __align__(16) float s_w[2][16][64];
    int t = threadIdx.x;
    int p0 = blockIdx.x * 128, oc0 = blockIdx.y * 64, b = blockIdx.z;
    int ocg = t >> 5, pp = (t & 31) * 4;

    for (int idx = t; idx < 2048; idx += 256) {
        int ic = idx >> 7, p = idx & 127;
        float v = in[(b*256 + ic)*1024 + p0 + p];
        s_in[0][ic][p] = v > 0.0f ? v : 0.0f;
    }
    for (int idx = t; idx < 1024; idx += 256) {
        int oc_l = idx >> 4, ic = idx & 15;
        s_w[0][ic][oc_l] = w[(oc0 + oc_l)*256 + ic];
    }
    __syncthreads();

    u64 acc2[4][4];
    #pragma unroll
    for (int i = 0; i < 4; i++)
        #pragma unroll
        for (int j = 0; j < 4; j++) acc2[i][j] = pk2(0.0f, 0.0f);

    for (int ch = 0; ch < 16; ch++) {
        int cur = ch & 1;
        float rin[8], rw[4];
        if (ch < 15) {
            int ic0 = (ch + 1) * 16;
            #pragma unroll
            for (int s = 0; s < 8; s++) {
                int idx = t + s*256;
                float v = in[(b*256 + ic0 + (idx >> 7))*1024 + p0 + (idx & 127)];
                rin[s] = v > 0.0f ? v : 0.0f;
            }
            #pragma unroll
            for (int s = 0; s < 4; s++) {
                int idx = t + s*256;
                rw[s] = w[(oc0 + (idx >> 4))*256 + ic0 + (idx & 15)];
            }
        }

        #pragma unroll
        for (int k = 0; k < 16; k++) {
            float4 ivv = *(const float4*)&s_in[cur][k][pp];
            u64 ivp[4] = {pk2(ivv.x,ivv.x), pk2(ivv.y,ivv.y), pk2(ivv.z,ivv.z), pk2(ivv.w,ivv.w)};
            float4 w0 = *(const float4*)&s_w[cur][k][ocg*8];
            float4 w1 = *(const float4*)&s_w[cur][k][ocg*8 + 4];
            u64 wp[4] = {pk2(w0.x,w0.y), pk2(w0.z,w0.w), pk2(w1.x,w1.y), pk2(w1.z,w1.w)};
            #pragma unroll
            for (int i2 = 0; i2 < 4; i2++)
                #pragma unroll
                for (int j = 0; j < 4; j++) fma2(acc2[i2][j], wp[i2], ivp[j]);
        }

        if (ch < 15) {
            int nxt = cur ^ 1;
            #pragma unroll
            for (int s = 0; s < 8; s++) {
                int idx = t + s*256;
                s_in[nxt][idx >> 7][idx & 127] = rin[s];
            }
            #pragma unroll
            for (int s = 0; s < 4; s++) {
                int idx = t + s*256;
                s_w[nxt][idx & 15][idx >> 4] = rw[s];
            }
        }
        __syncthreads();
    }

    #pragma unroll
    for (int i2 = 0; i2 < 4; i2++) {
        float2 q0 = up2(acc2[i2][0]), q1 = up2(acc2[i2][1]);
        float2 q2 = up2(acc2[i2][2]), q3 = up2(acc2[i2][3]);
        int ocA = oc0 + ocg*8 + 2*i2, ocB = ocA + 1;
        float4 rA = *(const float4*)&resid[(b*256 + ocA)*1024 + p0 + pp];
        float4 rB = *(const float4*)&resid[(b*256 + ocB)*1024 + p0 + pp];
        float4 oA = make_float4(q0.x+rA.x, q1.x+rA.y, q2.x+rA.z, q3.x+rA.w);
        float4 oB = make_float4(q0.y+rB.x, q1.y+rB.y, q2.y+rB.z, q3.y+rB.w);
        *(float4*)&out[(b*256 + ocA)*1024 + p0 + pp] = oA;
        *(float4*)&out[(b*256 + ocB)*1024 + p0 + pp] = oB;
    }
}

// ---------------- VQ: fp32 replica of reference distance (FROZEN) ----------
__global__ __launch_bounds__(256) void k_vq(const float* __restrict__ in,
                                            const float* __restrict__ cb,
                                            float* __restrict__ out) {
    __shared__ __align__(16) float s_v[64][65];
    __shared__ float s_vn[64];
    __shared__ float s_cn[64];
    __shared__ float s_dist[64];
    __shared__ int   s_fidx[64];
    __shared__ __align__(16) float s_cbuf[64*65];

    int t = threadIdx.x;
    int px0 = blockIdx.x * 64, cbk = blockIdx.y, b = blockIdx.z;
    const float* base = in + (b*256 + cbk*64)*1024 + px0;

    for (int idx = t; idx < 4096; idx += 256) {
        int j = idx >> 6, i = idx & 63;
        s_v[i][j] = base[j*1024 + i];
    }
    __syncthreads();
    if (t < 64) {
        float s = 0.0f;
        for (int j = 0; j < 64; j++) { float v = s_v[t][j]; s = __fmaf_rn(v, v, s); }
        s_vn[t] = s;
    }
    __syncthreads();

    int i0 = (t & 7) * 8;
    int g  = t >> 3;
    float vn[8];
    #pragma unroll
    for (int ii = 0; ii < 8; ii++) vn[ii] = s_vn[i0 + ii];

    float best[8]; int bidx[8];
    #pragma unroll
    for (int ii = 0; ii < 8; ii++) { best[ii] = 3.4e38f; bidx[ii] = 0x7fffffff; }

    for (int chunk = 0; chunk < 4; chunk++) {
        __syncthreads();
        for (int idx = t; idx < 4096; idx += 256) {
            int cc = idx >> 6, j = idx & 63;
            s_cbuf[cc*65 + j] = cb[(chunk*64 + cc)*64 + j];
        }
        __syncthreads();
        if (t < 64) {
            float s = 0.0f;
            for (int j = 0; j < 64; j++) { float e = s_cbuf[t*65 + j]; s = __fmaf_rn(e, e, s); }
            s_cn[t] = s;
        }
        __syncthreads();

        int cc0 = g * 2;
        float d0[8], d1[8];
        #pragma unroll
        for (int ii = 0; ii < 8; ii++) { d0[ii] = 0.0f; d1[ii] = 0.0f; }
        for (int k = 0; k < 64; k++) {
            float c0 = s_cbuf[cc0*65 + k];
            float c1 = s_cbuf[(cc0+1)*65 + k];
            #pragma unroll
            for (int ii = 0; ii < 8; ii++) {
                float vv = s_v[i0 + ii][k];
                d0[ii] = __fmaf_rn(vv, c0, d0[ii]);
                d1[ii] = __fmaf_rn(vv, c1, d1[ii]);
            }
        }
        float n0 = s_cn[cc0], n1 = s_cn[cc0+1];
        #pragma unroll
        for (int ii = 0; ii < 8; ii++) {
            float sc0 = __fsub_rn(__fadd_rn(vn[ii], n0), __fmul_rn(2.0f, d0[ii]));
            if (sc0 < best[ii]) { best[ii] = sc0; bidx[ii] = chunk*64 + cc0; }
            float sc1 = __fsub_rn(__fadd_rn(vn[ii], n1), __fmul_rn(2.0f, d1[ii]));
            if (sc1 < best[ii]) { best[ii] = sc1; bidx[ii] = chunk*64 + cc0 + 1; }
        }
    }
    __syncthreads();

    float* rv = s_cbuf;
    int*   ri = (int*)(s_cbuf + 2048);
    #pragma unroll
    for (int ii = 0; ii < 8; ii++) {
        rv[g*64 + i0 + ii] = best[ii];
        ri[g*64 + i0 + ii] = bidx[ii];
    }
    __syncthreads();

    if (t < 64) {
        float bb = 3.4e38f; int bi = 0x7fffffff;
        for (int gg = 0; gg < 32; gg++) {
            float v = rv[gg*64 + t];
            int  id = ri[gg*64 + t];
            if (v < bb || (v == bb && id < bi)) { bb = v; bi = id; }
        }
        s_fidx[t] = bi;
        s_dist[t] = bb;
    }
    __syncthreads();
    if (t == 0) {
        float s = 0.0f;
        for (int v = 0; v < 64; v++) s += s_dist[v];
        atomicAdd(&g_loss, s);
    }

    for (int idx = t; idx < 4096; idx += 256) {
        int j = idx >> 6, i = idx & 63;
        out[(b*256 + cbk*64 + j)*1024 + px0 + i] = cb[s_fidx[i]*64 + j];
    }
}

// ------- deconv1: 256->256, transposed (wide tile, 2 CTAs/SM) --------------
__global__ __launch_bounds__(256, 2) void k_deconv1(const float* __restrict__ in,
                                                    const float* __restrict__ w,
                                                    const float* __restrict__ bias) {
    __shared__ __align__(16) float s_in[2][4][9][33];
    __shared__ __align__(16) float s_w[2][4][4][64];
    int t = threadIdx.x;
    int r0 = blockIdx.x * 8, oc0 = blockIdx.y * 64;
    int bz = blockIdx.z, b = bz >> 2, cls = bz & 3, py = cls >> 1, qx = cls & 1;
    int ocg = t >> 5, lane = t & 31;
    int row = lane >> 2, col = (lane & 3) * 8;

    for (int idx = t; idx < 1188; idx += 256) {
        int ic = idx / 297, rem = idx % 297, rowi = rem / 33, coli = rem % 33;
        int ir = r0 + py - 1 + rowi, icc = qx - 1 + coli;
        float v = 0.0f;
        if (ir >= 0 && ir < 32 && icc >= 0 && icc < 32)
            v = in[((b*256 + ic)*32 + ir)*32 + icc];
        s_in[0][ic][rowi][coli] = v;
    }
    for (int idx = t; idx < 1024; idx += 256) {
        int ic = idx >> 8, rem = idx & 255, oc_l = rem >> 2, tp = rem & 3;
        int dy = tp >> 1, dx = tp & 1;
        s_w[0][ic][tp][oc_l] =
            w[(ic*256 + oc0 + oc_l)*16 + (3 - py - 2*dy)*4 + (3 - qx - 2*dx)];
    }
    __syncthreads();

    u64 acc2[4][8];
    #pragma unroll
    for (int i = 0; i < 4; i++)
        #pragma unroll
        for (int j = 0; j < 8; j++) acc2[i][j] = pk2(0.0f, 0.0f);

    for (int ch = 0; ch < 64; ch++) {
        int cur = ch & 1;
        float rin[5], rw[4];
        if (ch < 63) {
            int ic0 = (ch + 1) * 4;
            #pragma unroll
            for (int s = 0; s < 5; s++) {
                int idx = t + s*256;
                float v = 0.0f;
                if (idx < 1188) {
                    int ic = idx / 297, rem = idx % 297, rowi = rem / 33, coli = rem % 33;
                    int ir = r0 + py - 1 + rowi, icc = qx - 1 + coli;
                    if (ir >= 0 && ir < 32 && icc >= 0 && icc < 32)
                        v = in[((b*256 + ic0 + ic)*32 + ir)*32 + icc];
                }
                rin[s] = v;
            }
            #pragma unroll
            for (int s = 0; s < 4; s++) {
                int idx = t + s*256;
                int ic = idx >> 8, rem = idx & 255, oc_l = rem >> 2, tp = rem & 3;
                int dy = tp >> 1, dx = tp & 1;
                rw[s] = w[((ic0 + ic)*256 + oc0 + oc_l)*16 + (3 - py - 2*dy)*4 + (3 - qx - 2*dx)];
            }
        }

        #pragma unroll
        for (int ic = 0; ic < 4; ic++)
            #pragma unroll
            for (int dy = 0; dy < 2; dy++) {
                float iv[9];
                #pragma unroll
                for (int m = 0; m < 9; m++)
                    iv[m] = s_in[cur][ic][row + dy][col + m];
                u64 ivp[9];
                #pragma unroll
                for (int m = 0; m < 9; m++) ivp[m] = pk2(iv[m], iv[m]);
                #pragma unroll
                for (int dx = 0; dx < 2; dx++) {
                    float4 w0 = *(const float4*)&s_w[cur][ic][dy*2 + dx][ocg*8];
                    float4 w1 = *(const float4*)&s_w[cur][ic][dy*2 + dx][ocg*8 + 4];
                    u64 wp[4] = {pk2(w0.x,w0.y), pk2(w0.z,w0.w), pk2(w1.x,w1.y), pk2(w1.z,w1.w)};
                    #pragma unroll
                    for (int i2 = 0; i2 < 4; i2++)
                        #pragma unroll
                        for (int j = 0; j < 8; j++) fma2(acc2[i2][j], wp[i2], ivp[j + dx]);
                }
            }

        if (ch < 63) {
            int nxt = cur ^ 1;
            #pragma unroll
            for (int s = 0; s < 5; s++) {
                int idx = t + s*256;
                if (idx < 1188) {
                    int ic = idx / 297, rem = idx % 297;
                    s_in[nxt][ic][rem / 33][rem % 33] = rin[s];
                }
            }
            #pragma unroll
            for (int s = 0; s < 4; s++) {
                int idx = t + s*256;
                int ic = idx >> 8, rem = idx & 255;
                s_w[nxt][ic][rem & 3][rem >> 2] = rw[s];
            }
        }
        __syncthreads();
    }

    int oy = 2*(r0 + row) + py;
    #pragma unroll
    for (int i2 = 0; i2 < 4; i2++) {
        float2 q[8];
        #pragma unroll
        for (int j = 0; j < 8; j++) q[j] = up2(acc2[i2][j]);
        int ocA = oc0 + ocg*8 + 2*i2, ocB = ocA + 1;
        float bA = bias[ocA], bB = bias[ocB];
        #pragma unroll
        for (int j = 0; j < 8; j++) {
            int ox = 2*(col + j) + qx;
            g_z1[((b*256 + ocA)*64 + oy)*64 + ox] = q[j].x + bA;
            g_z1[((b*256 + ocB)*64 + oy)*64 + ox] = q[j].y + bB;
        }
    }
}

// ------- deconv2: 256->3, transposed, 64->128, +bias, tanh (pipelined) -----
__global__ __launch_bounds__(256, 2) void k_deconv2(const float* __restrict__ w,
                                                    const float* __restrict__ bias,
                                                    float* __restrict__ out) {
    __shared__ float s_in[2][4][17][69];
    __shared__ float s_w[2][4][4][3];
    int t = threadIdx.x;
    int r0 = blockIdx.x * 16;
    int bz = blockIdx.z, b = bz >> 2, cls = bz & 3, py = cls >> 1, qx = cls & 1;
    int pv = t * 4, row = pv >> 6, col = pv & 63;

    for (int idx = t; idx < 4420; idx += 256) {
        int ic = idx / 1105, rem = idx % 1105, rowi = rem / 65, coli = rem % 65;
        int ir = r0 + py - 1 + rowi, icc = qx - 1 + coli;
        float v = 0.0f;
        if (ir >= 0 && ir < 64 && icc >= 0 && icc < 64)
            v = g_z1[((b*256 + ic)*64 + ir)*64 + icc];
        s_in[0][ic][rowi][coli] = v;
    }
    if (t < 48) {
        int ic = t / 12, rem = t % 12, oc = rem / 4, tp = rem & 3;
        int dy = tp >> 1, dx = tp & 1;
        s_w[0][ic][tp][oc] =
            w[(ic*3 + oc)*16 + (3 - py - 2*dy)*4 + (3 - qx - 2*dx)];
    }
    __syncthreads();

    float acc[3][4];
    #pragma unroll
    for (int i = 0; i < 3; i++)
        #pragma unroll
        for (int j = 0; j < 4; j++) acc[i][j] = 0.0f;

    for (int ch = 0; ch < 64; ch++) {
        int cur = ch & 1;
        float rin[18], rwv = 0.0f;
        if (ch < 63) {
            int ic0n = (ch + 1) * 4;
            #pragma unroll
            for (int s = 0; s < 18; s++) {
                int idx = t + s*256;
                float v = 0.0f;
                if (idx < 4420) {
                    int ic = idx / 1105, rem = idx % 1105, rowi = rem / 65, coli = rem % 65;
                    int ir = r0 + py - 1 + rowi, icc = qx - 1 + coli;
                    if (ir >= 0 && ir < 64 && icc >= 0 && icc < 64)
                        v = g_z1[((b*256 + ic0n + ic)*64 + ir)*64 + icc];
                }
                rin[s] = v;
            }
            if (t < 48) {
                int ic = t / 12, rem = t % 12, oc = rem / 4, tp = rem & 3;
                int dy = tp >> 1, dx = tp & 1;
                rwv = w[((ic0n + ic)*3 + oc)*16 + (3 - py - 2*dy)*4 + (3 - qx - 2*dx)];
            }
        }

        #pragma unroll
        for (int ic = 0; ic < 4; ic++)
            #pragma unroll
            for (int dy = 0; dy < 2; dy++) {
                float iv5[5];
                #pragma unroll
                for (int m = 0; m < 5; m++)
                    iv5[m] = s_in[cur][ic][row + dy][col + m];
                #pragma unroll
                for (int dx = 0; dx < 2; dx++) {
                    #pragma unroll
                    for (int oc = 0; oc < 3; oc++) {
                        float wv = s_w[cur][ic][dy*2 + dx][oc];
                        #pragma unroll
                        for (int j = 0; j < 4; j++) acc[oc][j] += wv * iv5[j + dx];
                    }
                }
            }

        if (ch < 63) {
            int nxt = cur ^ 1;
            #pragma unroll
            for (int s = 0; s < 18; s++) {
                int idx = t + s*256;
                if (idx < 4420) {
                    int ic = idx / 1105, rem = idx % 1105;
                    s_in[nxt][ic][rem / 65][rem % 65] = rin[s];
                }
            }
            if (t < 48) {
                int ic = t / 12, rem = t % 12, oc = rem / 4, tp = rem & 3;
                s_w[nxt][ic][tp][oc] = rwv;
            }
        }
        __syncthreads();
    }

    int oy = 2*(r0 + row) + py;
    #pragma unroll
    for (int oc = 0; oc < 3; oc++) {
        float bv = bias[oc];
        #pragma unroll
        for (int j = 0; j < 4; j++) {
            int ox = 2*(col + j) + qx;
            out[((b*3 + oc)*128 + oy)*128 + ox] = tanhf(acc[oc][j] + bv);
        }
    }
}

__global__ void k_finalize(float* out, int n) {
    out[n - 1] = 1.25f * g_loss / 8388608.0f;
}

// ---------------------------------------------------------------------------
extern "C" void kernel_launch(void* const* d_in, const int* in_sizes, int n_in,
                              void* d_out, int out_size) {
    const float* x       = (const float*)d_in[0];
    const float* enc_w1  = (const float*)d_in[1];
    const float* enc_b1  = (const float*)d_in[2];
    const float* enc_w2  = (const float*)d_in[3];
    const float* enc_b2  = (const float*)d_in[4];
    const float* er1_w3  = (const float*)d_in[5];
    const float* er1_w1  = (const float*)d_in[6];
    const float* er2_w3  = (const float*)d_in[7];
    const float* er2_w1  = (const float*)d_in[8];
    const float* codebook= (const float*)d_in[9];
    const float* dr1_w3  = (const float*)d_in[10];
    const float* dr1_w1  = (const float*)d_in[11];
    const float* dr2_w3  = (const float*)d_in[12];
    const float* dr2_w1  = (const float*)d_in[13];
    const float* dt1_w   = (const float*)d_in[14];
    const float* dt1_b   = (const float*)d_in[15];
    const float* dt2_w   = (const float*)d_in[16];
    const float* dt2_b   = (const float*)d_in[17];
    float* out = (float*)d_out;

    float *pA, *pB, *pC;
    cudaGetSymbolAddress((void**)&pA, g_A);
    cudaGetSymbolAddress((void**)&pB, g_B);
    cudaGetSymbolAddress((void**)&pC, g_C);

    k_zero_loss<<<1, 1>>>();

    // encoder
    k_conv1<<<dim3(32, 4, 32), 256>>>(x, enc_w1, enc_b1);
    k_conv2<<<dim3(4, 4, 32), 256>>>(enc_w2, enc_b2, pA);
    k_conv3<<<dim3(4, 4, 32), 256>>>(pA, er1_w3, pB);
    k_c1x1 <<<dim3(8, 4, 32), 256>>>(pB, er1_w1, pA, pC);
    k_conv3<<<dim3(4, 4, 32), 256>>>(pC, er2_w3, pB);
    k_c1x1 <<<dim3(8, 4, 32), 256>>>(pB, er2_w1, pC, pA);

    // VQ
    k_vq<<<dim3(16, 4, 32), 256>>>(pA, codebook, pC);

    // decoder
    k_conv3<<<dim3(4, 4, 32), 256>>>(pC, dr1_w3, pB);
    k_c1x1 <<<dim3(8, 4, 32), 256>>>(pB, dr1_w1, pC, pA);
    k_conv3<<<dim3(4, 4, 32), 256>>>(pA, dr2_w3, pB);
    k_c1x1 <<<dim3(8, 4, 32), 256>>>(pB, dr2_w1, pA, pC);
    k_deconv1<<<dim3(4, 4, 128), 256>>>(pC, dt1_w, dt1_b);
    k_deconv2<<<dim3(4, 1, 128), 256>>>(dt2_w, dt2_b, out);

    k_finalize<<<1, 1>>>(out, out_size);
}